// round 15
// baseline (speedup 1.0000x reference)
#include <cuda_runtime.h>
#include <cuda_bf16.h>
#include <cstdint>

// SoftPerspectiveShader: fused sample_textures + softmax_rgb_blend
// R14 = R13 with the pipeline cursor bug fixed. R13's consume cursor
// rotated over 4 slots while refills only ever landed in slots {0,1,2}
// (refill-into-consumed-slot), so every 4th read hit a never-written slot
// (rel_err 0.43). Fix: STAGES=3 rotation matching the 3 prologue fills.
//
// Theory (unchanged): the LDG path is capped by the ~248-entry L1tex
// queue (R1: 40w x 6 = 240 -> DRAM 66%; R7: 48w x 6 = 288 overflow ->
// worse). Covering ~320ns DRAM latency at ~54GB/s/SM needs ~17KB/SM in
// flight. cp.async.cg bypasses L1 + register landing: 3 pending groups
// x 96B x 512 thr/SM = 147KB/SM in flight. 128-thr blocks, 36KB SMEM,
// 608 persistent blocks (4/SM), per-thread groups -> NO barriers.
// Compute body bit-identical to R1 (rel_err 4.2969e-7). Softmax is
// effectively one-hot (GAMMA=1e-4, zbuf sorted): w==0 fragments
// contribute exactly 0, so their bary/fcol gathers are skipped.

#define SIGMA_F 1e-4f
#define GAMMA_F 1e-4f
#define ZNEAR_F 1.0f
#define ZFAR_F  100.0f
#define EPS_F   1e-10f

#define THREADS 128
#define STAGES  3
#define NBLOCKS 608   // 4 blocks/SM x 152 SMs, persistent

__device__ __forceinline__ uint32_t smem_u32(const void* p) {
    uint32_t a;
    asm("{ .reg .u64 t; cvta.to.shared.u64 t, %1; cvt.u32.u64 %0, t; }"
        : "=r"(a) : "l"(p));
    return a;
}

__device__ __forceinline__ void cpa16(uint32_t dst, const void* src) {
    asm volatile("cp.async.cg.shared.global [%0], [%1], 16;"
                 :: "r"(dst), "l"(src) : "memory");
}

__global__ __launch_bounds__(THREADS) void soft_shader_pipe(
    const float4* __restrict__ p2f4,   // pix_to_face as float4 [P/4*2]
    const float*  __restrict__ bary,   // [P][8][3]
    const float4* __restrict__ zbuf,   // [P/4*2]
    const float4* __restrict__ dists,  // [P/4*2]
    const float*  __restrict__ fcol,   // [F][3][3]
    float4*       __restrict__ out,    // [P]
    int nchunks)                       // P / THREADS
{
    // 3 stages x 6 vectors x 128 threads x 16B = 36KB
    __shared__ float4 sbuf[STAGES][6][THREADS];

    const int t    = threadIdx.x;
    const int nblk = gridDim.x;

    // stage chunk c into slot s (per-thread: 6 x cp.async 16B); ALWAYS
    // commit a group (possibly empty) so per-thread group counts align.
    auto stage = [&](int c, int s) {
        if (c < nchunks) {
            size_t px = (size_t)c * THREADS + t;
            cpa16(smem_u32(&sbuf[s][0][t]), p2f4  + 2 * px);
            cpa16(smem_u32(&sbuf[s][1][t]), p2f4  + 2 * px + 1);
            cpa16(smem_u32(&sbuf[s][2][t]), zbuf  + 2 * px);
            cpa16(smem_u32(&sbuf[s][3][t]), zbuf  + 2 * px + 1);
            cpa16(smem_u32(&sbuf[s][4][t]), dists + 2 * px);
            cpa16(smem_u32(&sbuf[s][5][t]), dists + 2 * px + 1);
        }
        asm volatile("cp.async.commit_group;" ::: "memory");
    };

    const int c0 = blockIdx.x;
    stage(c0,            0);   // group A -> slot 0
    stage(c0 + nblk,     1);   // group B -> slot 1
    stage(c0 + 2 * nblk, 2);   // group C -> slot 2

    int s = 0;
#pragma unroll 1
    for (int c = c0; c < nchunks; c += nblk) {
        // 3 groups pending; wait until <=2 -> the group that filled slot s
        // (the oldest) is complete. Per-thread ordering, no barrier.
        asm volatile("cp.async.wait_group 2;" ::: "memory");

        const float4 vf0 = sbuf[s][0][t], vf1 = sbuf[s][1][t];
        const float4 vz0 = sbuf[s][2][t], vz1 = sbuf[s][3][t];
        const float4 vd0 = sbuf[s][4][t], vd1 = sbuf[s][5][t];

        // refill the slot just consumed with chunk c + 3*nblk: it will be
        // read exactly 3 iterations from now (rotation modulus == 3).
        stage(c + STAGES * nblk, s);
        s = (s == STAGES - 1) ? 0 : s + 1;

        int faces[8] = { __float_as_int(vf0.x), __float_as_int(vf0.y),
                         __float_as_int(vf0.z), __float_as_int(vf0.w),
                         __float_as_int(vf1.x), __float_as_int(vf1.y),
                         __float_as_int(vf1.z), __float_as_int(vf1.w) };
        float zv[8] = { vz0.x, vz0.y, vz0.z, vz0.w, vz1.x, vz1.y, vz1.z, vz1.w };
        float dv[8] = { vd0.x, vd0.y, vd0.z, vd0.w, vd1.x, vd1.y, vd1.z, vd1.w };

        const size_t p = (size_t)c * THREADS + t;

        float prob[8], zinv[8];
        float zmax = EPS_F;      // z_inv_max = max(max_k z_inv, EPS)
        float keep = 1.0f;       // prod(1 - prob) = 1 - alpha

#pragma unroll
        for (int k = 0; k < 8; k++) {
            bool  m  = faces[k] >= 0;
            // sigmoid(-d/sigma) = 1/(1+exp(d/sigma))
            float pr = m ? (1.0f / (1.0f + expf(dv[k] / SIGMA_F))) : 0.0f;
            prob[k] = pr;
            keep *= (1.0f - pr);
            float zi = m ? ((ZFAR_F - zv[k]) / (ZFAR_F - ZNEAR_F)) : 0.0f;
            zinv[k] = zi;
            zmax = fmaxf(zmax, zi);
        }

        float delta = fmaxf(expf((EPS_F - zmax) / GAMMA_F), EPS_F);
        float denom = delta;
        float r = 0.0f, g = 0.0f, b = 0.0f;

#pragma unroll
        for (int k = 0; k < 8; k++) {
            float w = prob[k] * expf((zinv[k] - zmax) / GAMMA_F);
            denom += w;
            if (w > 0.0f) {
                // w > 0 implies faces[k] >= 0
                const float* bc = bary + p * 24 + (size_t)k * 3;
                float b0 = bc[0], b1 = bc[1], b2 = bc[2];
                const float* fc = fcol + (size_t)faces[k] * 9;
                float t0 = b0 * fc[0] + b1 * fc[3] + b2 * fc[6];
                float t1 = b0 * fc[1] + b1 * fc[4] + b2 * fc[7];
                float t2 = b0 * fc[2] + b1 * fc[5] + b2 * fc[8];
                r += w * t0;
                g += w * t1;
                b += w * t2;
            }
        }

        float inv = 1.0f / denom;
        float4 o;
        o.x = (r + delta) * inv;   // background = (1,1,1): + delta*1/denom
        o.y = (g + delta) * inv;
        o.z = (b + delta) * inv;
        o.w = keep;                // 1 - alpha
        out[p] = o;
    }
}

extern "C" void kernel_launch(void* const* d_in, const int* in_sizes, int n_in,
                              void* d_out, int out_size) {
    const float4* p2f4  = (const float4*)d_in[0];
    const float*  bary  = (const float*)d_in[1];
    const float4* zbufp = (const float4*)d_in[2];
    const float4* dist  = (const float4*)d_in[3];
    const float*  fcol  = (const float*)d_in[4];
    int P = in_sizes[0] / 8;          // N*H*W pixels (1,048,576)
    int nchunks = P / THREADS;        // 8192 (P divisible by 128)

    soft_shader_pipe<<<NBLOCKS, THREADS>>>(
        p2f4, bary, zbufp, dist, fcol, (float4*)d_out, nchunks);
}

// round 16
// speedup vs baseline: 1.5628x; 1.5628x over previous
#include <cuda_runtime.h>
#include <cuda_fp16.h>
#include <cuda_bf16.h>
#include <cstdint>

// SoftPerspectiveShader: fused sample_textures + softmax_rgb_blend
// R15: sector-exact face-color table. 14 rounds established: when DRAM is
// busy it runs at ~7.8TB/s (spec); the only lever left is TRAFFIC
// (218MB measured vs ~150MB floor). The excess matches fcol gather
// re-misses: 36B misaligned rows -> 2 sectors (64B) per random gather,
// with the 7.2MB table continuously evicted by 192MB/launch of stream
// turnover. Fix: prologue converts face_colors to fp16 rows padded to
// exactly one aligned 32B sector (9 halfs = 18B payload); main-kernel
// gather becomes 2 loads (16B+4B) touching 1 sector. fp16 error on
// colors in [0,1] is <=2.4e-4 rel, far under the 1e-3 threshold.
// Main kernel is otherwise byte-for-byte R1 (best: 43.5us).

#define SIGMA_F 1e-4f
#define GAMMA_F 1e-4f
#define ZNEAR_F 1.0f
#define ZFAR_F  100.0f
#define EPS_F   1e-10f
#define MAX_F   200000

// [F][16] halfs: 32B-aligned rows, one DRAM sector per gather. 6.4MB.
__device__ __align__(32) __half g_fcol16[(size_t)MAX_F * 16];

__global__ __launch_bounds__(256) void cvt_fcol_kernel(
    const float* __restrict__ fcol, int total)   // total = F*9
{
    int i = blockIdx.x * blockDim.x + threadIdx.x;
    if (i >= total) return;
    int f = i / 9, c = i - 9 * f;
    g_fcol16[(size_t)f * 16 + c] = __float2half(fcol[i]);  // coalesced read
}

__device__ __forceinline__ float2 h2f(uint32_t u) {
    __half2 h = *reinterpret_cast<__half2*>(&u);
    return __half22float2(h);
}

__global__ __launch_bounds__(256) void soft_shader_kernel(
    const int4*   __restrict__ p2f,    // [P][2] int4  (K=8)
    const float*  __restrict__ bary,   // [P][8][3]
    const float4* __restrict__ zbuf,   // [P][2] float4
    const float4* __restrict__ dists,  // [P][2] float4
    float4*       __restrict__ out,    // [P]
    int P)
{
    int p = blockIdx.x * blockDim.x + threadIdx.x;
    if (p >= P) return;

    // ---- front batch: 6 independent LDG.128 (R1 ordering) ----
    const int4   fa = p2f[2 * p],   fb = p2f[2 * p + 1];
    const float4 za = zbuf[2 * p],  zb = zbuf[2 * p + 1];
    const float4 da = dists[2 * p], db = dists[2 * p + 1];

    int   faces[8] = {fa.x, fa.y, fa.z, fa.w, fb.x, fb.y, fb.z, fb.w};
    float zv[8]    = {za.x, za.y, za.z, za.w, zb.x, zb.y, zb.z, zb.w};
    float dv[8]    = {da.x, da.y, da.z, da.w, db.x, db.y, db.z, db.w};

    float prob[8], zinv[8];
    float zmax = EPS_F;      // z_inv_max = max(max_k z_inv, EPS)
    float keep = 1.0f;       // prod(1 - prob) = 1 - alpha

#pragma unroll
    for (int k = 0; k < 8; k++) {
        bool  m  = faces[k] >= 0;
        // sigmoid(-d/sigma) = 1/(1+exp(d/sigma)); matches jax stable sigmoid
        float pr = m ? (1.0f / (1.0f + expf(dv[k] / SIGMA_F))) : 0.0f;
        prob[k] = pr;
        keep *= (1.0f - pr);
        float zi = m ? ((ZFAR_F - zv[k]) / (ZFAR_F - ZNEAR_F)) : 0.0f;
        zinv[k] = zi;
        zmax = fmaxf(zmax, zi);
    }

    float delta = fmaxf(expf((EPS_F - zmax) / GAMMA_F), EPS_F);
    float denom = delta;
    float r = 0.0f, g = 0.0f, b = 0.0f;

#pragma unroll
    for (int k = 0; k < 8; k++) {
        float w = prob[k] * expf((zinv[k] - zmax) / GAMMA_F);
        denom += w;
        if (w > 0.0f) {
            // w > 0 implies faces[k] >= 0
            const float* bc = bary + (size_t)p * 24 + (size_t)k * 3;
            float b0 = bc[0], b1 = bc[1], b2 = bc[2];
            // one-sector gather: 16B + 4B from the 32B-aligned fp16 row
            const __half* rowp = g_fcol16 + ((size_t)faces[k] << 4);
            uint4    u = *(const uint4*)rowp;          // h0..h7
            uint32_t v = *(const uint32_t*)(rowp + 8); // h8 (+pad)
            float2 A = h2f(u.x), B = h2f(u.y), C = h2f(u.z), D = h2f(u.w);
            float2 E = h2f(v);
            // row-major [3 verts][3 ch]: v0=(h0,h1,h2) v1=(h3,h4,h5) v2=(h6,h7,h8)
            float t0 = b0 * A.x + b1 * B.y + b2 * D.x;
            float t1 = b0 * A.y + b1 * C.x + b2 * D.y;
            float t2 = b0 * B.x + b1 * C.y + b2 * E.x;
            r += w * t0;
            g += w * t1;
            b += w * t2;
        }
    }

    float inv = 1.0f / denom;
    float4 o;
    o.x = (r + delta) * inv;   // background = (1,1,1): + delta*1/denom
    o.y = (g + delta) * inv;
    o.z = (b + delta) * inv;
    o.w = keep;                // 1 - alpha
    out[p] = o;
}

extern "C" void kernel_launch(void* const* d_in, const int* in_sizes, int n_in,
                              void* d_out, int out_size) {
    const int*   p2f   = (const int*)d_in[0];
    const float* bary  = (const float*)d_in[1];
    const float* zbufp = (const float*)d_in[2];
    const float* dist  = (const float*)d_in[3];
    const float* fcol  = (const float*)d_in[4];
    int P     = in_sizes[0] / 8;   // N*H*W pixels
    int total = in_sizes[4];       // F*9 floats

    cvt_fcol_kernel<<<(total + 255) / 256, 256>>>(fcol, total);

    int threads = 256;
    int blocks  = (P + threads - 1) / threads;
    soft_shader_kernel<<<blocks, threads>>>(
        (const int4*)p2f, bary, (const float4*)zbufp, (const float4*)dist,
        (float4*)d_out, P);
}

// round 17
// speedup vs baseline: 2.3240x; 1.4870x over previous
#include <cuda_runtime.h>
#include <cuda_bf16.h>

// SoftPerspectiveShader: fused sample_textures + softmax_rgb_blend
// R16 = R1 byte-for-byte body + persistent grid-stride loop. ONLY ONE
// VARIABLE vs R1 (best: 43.5us): grid = 760 blocks (5/SM x 152 SMs, one
// wave) instead of 4096 blocks in 5.5 waves, removing ~5 wave transitions
// (~2360cyc each) and per-wave ramp/drain. Default cache ops everywhere
// (R11's regression traced to .cs on the scalar bary loads, not to
// persistence). Arithmetic bit-identical to R1: expect rel_err 4.2969e-7.
// Softmax is effectively one-hot (GAMMA=1e-4, zbuf sorted ascending):
// w==0 fragments contribute exactly 0, so their bary/fcol gathers are
// skipped.

#define SIGMA_F 1e-4f
#define GAMMA_F 1e-4f
#define ZNEAR_F 1.0f
#define ZFAR_F  100.0f
#define EPS_F   1e-10f

#define THREADS 256
#define NBLOCKS 760   // 5 blocks/SM x 152 SMs: one persistent wave

__global__ __launch_bounds__(THREADS, 5) void soft_shader_kernel(
    const int4*   __restrict__ p2f,    // [P][2] int4  (K=8)
    const float*  __restrict__ bary,   // [P][8][3]
    const float4* __restrict__ zbuf,   // [P][2] float4
    const float4* __restrict__ dists,  // [P][2] float4
    const float*  __restrict__ fcol,   // [F][3][3]
    float4*       __restrict__ out,    // [P]
    int P)
{
    const int stride = gridDim.x * blockDim.x;

#pragma unroll 1
    for (int p = blockIdx.x * blockDim.x + threadIdx.x; p < P; p += stride) {
        // ---- front batch: 6 independent LDG.128 (R1 ordering) ----
        const int4   fa = p2f[2 * p],   fb = p2f[2 * p + 1];
        const float4 za = zbuf[2 * p],  zb = zbuf[2 * p + 1];
        const float4 da = dists[2 * p], db = dists[2 * p + 1];

        int   faces[8] = {fa.x, fa.y, fa.z, fa.w, fb.x, fb.y, fb.z, fb.w};
        float zv[8]    = {za.x, za.y, za.z, za.w, zb.x, zb.y, zb.z, zb.w};
        float dv[8]    = {da.x, da.y, da.z, da.w, db.x, db.y, db.z, db.w};

        float prob[8], zinv[8];
        float zmax = EPS_F;      // z_inv_max = max(max_k z_inv, EPS)
        float keep = 1.0f;       // prod(1 - prob) = 1 - alpha

#pragma unroll
        for (int k = 0; k < 8; k++) {
            bool  m  = faces[k] >= 0;
            // sigmoid(-d/sigma) = 1/(1+exp(d/sigma)); matches jax stable sigmoid
            float pr = m ? (1.0f / (1.0f + expf(dv[k] / SIGMA_F))) : 0.0f;
            prob[k] = pr;
            keep *= (1.0f - pr);
            float zi = m ? ((ZFAR_F - zv[k]) / (ZFAR_F - ZNEAR_F)) : 0.0f;
            zinv[k] = zi;
            zmax = fmaxf(zmax, zi);
        }

        float delta = fmaxf(expf((EPS_F - zmax) / GAMMA_F), EPS_F);
        float denom = delta;
        float r = 0.0f, g = 0.0f, b = 0.0f;

#pragma unroll
        for (int k = 0; k < 8; k++) {
            float w = prob[k] * expf((zinv[k] - zmax) / GAMMA_F);
            denom += w;
            if (w > 0.0f) {
                // w > 0 implies prob > 0 implies faces[k] >= 0
                const float* bc = bary + (size_t)p * 24 + (size_t)k * 3;
                float b0 = bc[0], b1 = bc[1], b2 = bc[2];
                const float* fc = fcol + (size_t)faces[k] * 9;
                float t0 = b0 * fc[0] + b1 * fc[3] + b2 * fc[6];
                float t1 = b0 * fc[1] + b1 * fc[4] + b2 * fc[7];
                float t2 = b0 * fc[2] + b1 * fc[5] + b2 * fc[8];
                r += w * t0;
                g += w * t1;
                b += w * t2;
            }
        }

        float inv = 1.0f / denom;
        float4 o;
        o.x = (r + delta) * inv;   // background = (1,1,1): + delta*1/denom
        o.y = (g + delta) * inv;
        o.z = (b + delta) * inv;
        o.w = keep;                // 1 - alpha
        out[p] = o;
    }
}

extern "C" void kernel_launch(void* const* d_in, const int* in_sizes, int n_in,
                              void* d_out, int out_size) {
    const int*   p2f   = (const int*)d_in[0];
    const float* bary  = (const float*)d_in[1];
    const float* zbufp = (const float*)d_in[2];
    const float* dist  = (const float*)d_in[3];
    const float* fcol  = (const float*)d_in[4];
    int P = in_sizes[0] / 8;   // N*H*W pixels

    soft_shader_kernel<<<NBLOCKS, THREADS>>>(
        (const int4*)p2f, bary, (const float4*)zbufp, (const float4*)dist,
        fcol, (float4*)d_out, P);
}